// round 2
// baseline (speedup 1.0000x reference)
#include <cuda_runtime.h>
#include <cuda_bf16.h>
#include <mma.h>
#include <cstdint>

using namespace nvcuda;

// Problem dims (fixed by the dataset)
#define T_STEPS 256
#define BATCH   128
#define N_INP   784
#define N_HID   512
#define N_OUT   128
#define M_TOTAL (T_STEPS * BATCH)   // 32768

#define KPAD1   832                 // 784 padded to 13*64
#define KPAD2   512                 // 512 = 8*64 exactly

// ---------------------------------------------------------------------------
// Scratch (static device globals -- sanctioned alloc-free scratch)
// ---------------------------------------------------------------------------
__device__ __align__(128) signed char g_wh_l0[N_HID * KPAD1];
__device__ __align__(128) signed char g_wh_l1[N_HID * KPAD1];
__device__ __align__(128) signed char g_wh_l2[N_HID * KPAD1];
__device__ __align__(128) signed char g_wo_l0[N_OUT * KPAD2];
__device__ __align__(128) signed char g_wo_l1[N_OUT * KPAD2];
__device__ __align__(128) signed char g_wo_l2[N_OUT * KPAD2];
__device__ __align__(128) signed char g_as8[(size_t)M_TOTAL * KPAD1];  // 27 MB packed spikes
__device__ __align__(128) float       g_ch[(size_t)M_TOTAL * N_HID];   // 64 MB
__device__ __align__(128) signed char g_sh[(size_t)M_TOTAL * N_HID];   // 16 MB
__device__ __align__(128) float       g_co[(size_t)M_TOTAL * N_OUT];   // 16 MB

// ---------------------------------------------------------------------------
// Spike pack: f32 (binary) -> s8, K padded 784->832 with zeros. 16B per thread.
// ---------------------------------------------------------------------------
__global__ void prep_spikes_kernel(const float* __restrict__ sp,
                                   signed char* __restrict__ out)
{
    const int CPR = KPAD1 / 16;                     // 52 chunks per row
    int idx = blockIdx.x * blockDim.x + threadIdx.x;
    if (idx >= M_TOTAL * CPR) return;
    int row = idx / CPR;
    int c   = idx - row * CPR;
    int4 val = make_int4(0, 0, 0, 0);
    if (c < N_INP / 16) {                           // chunks 0..48 fully in-range
        const float4* p = (const float4*)(sp + (size_t)row * N_INP + c * 16);
        float4 f0 = p[0], f1 = p[1], f2 = p[2], f3 = p[3];
        val.x = (f0.x > 0.5f) | ((f0.y > 0.5f) << 8) | ((f0.z > 0.5f) << 16) | ((f0.w > 0.5f) << 24);
        val.y = (f1.x > 0.5f) | ((f1.y > 0.5f) << 8) | ((f1.z > 0.5f) << 16) | ((f1.w > 0.5f) << 24);
        val.z = (f2.x > 0.5f) | ((f2.y > 0.5f) << 8) | ((f2.z > 0.5f) << 16) | ((f2.w > 0.5f) << 24);
        val.w = (f3.x > 0.5f) | ((f3.y > 0.5f) << 8) | ((f3.z > 0.5f) << 16) | ((f3.w > 0.5f) << 24);
    }
    ((int4*)out)[idx] = val;
}

// ---------------------------------------------------------------------------
// Weight -> 3x s8 limb decomposition (exact: w_q = (l2<<16|l1<<8|l0)*2^-22),
// padded along K with zeros.
// ---------------------------------------------------------------------------
__global__ void prep_limbs_kernel(const float* __restrict__ w,
                                  signed char* __restrict__ l0,
                                  signed char* __restrict__ l1,
                                  signed char* __restrict__ l2,
                                  int N, int K, int KP)
{
    int idx = blockIdx.x * blockDim.x + threadIdx.x;
    if (idx >= N * KP) return;
    int r = idx / KP;
    int c = idx - r * KP;
    signed char b0 = 0, b1 = 0, b2 = 0;
    if (c < K) {
        float s = w[(size_t)r * K + c] * 4194304.0f;      // 2^22
        s = fminf(fmaxf(s, -8323072.0f), 8323072.0f);
        int q  = __float2int_rn(s);
        b0 = (signed char)(q & 0xFF);  q = (q - (int)b0) >> 8;
        b1 = (signed char)(q & 0xFF);  q = (q - (int)b1) >> 8;
        b2 = (signed char)q;
    }
    l0[idx] = b0; l1[idx] = b1; l2[idx] = b2;
}

// ---------------------------------------------------------------------------
// cp.async helpers
// ---------------------------------------------------------------------------
__device__ __forceinline__ void cpa16(void* smem, const void* gmem) {
    uint32_t s = (uint32_t)__cvta_generic_to_shared(smem);
    asm volatile("cp.async.cg.shared.global [%0], [%1], 16;\n" :: "r"(s), "l"(gmem));
}
__device__ __forceinline__ void cpa_commit() {
    asm volatile("cp.async.commit_group;\n" ::: "memory");
}
template<int N>
__device__ __forceinline__ void cpa_wait() {
    asm volatile("cp.async.wait_group %0;\n" :: "n"(N) : "memory");
}

// ---------------------------------------------------------------------------
// Limb GEMM, pipelined: C[M,NTOT] = A[M,K] . B[N,K]^T reconstructed to fp32.
// BM=128, BN=64, BK=64, 2-stage cp.async double buffer, 8 warps (4x2),
// warp tile 32x32, 3 limb accumulators.
// ---------------------------------------------------------------------------
#define BM 128
#define BN 64
#define BK 64
#define ASTA 64   // A smem row stride
#define ASTB 80   // B smem row stride (padded vs LDSM conflicts)

template<int KTILES, int KPAD>
__global__ __launch_bounds__(256, 1)
void gemm_limb_kernel(const signed char* __restrict__ A,
                      const signed char* __restrict__ B0,
                      const signed char* __restrict__ B1,
                      const signed char* __restrict__ B2,
                      float* __restrict__ C, int NTOT)
{
    __shared__ __align__(128) signed char As[2][BM][ASTA];      // 16 KB
    __shared__ __align__(128) signed char Bs[2][3][BN][ASTB];   // 30 KB

    const int tid    = threadIdx.x;
    const int wid    = tid >> 5;
    const int warp_m = wid & 3;     // 0..3 (32 rows each)
    const int warp_n = wid >> 2;    // 0..1 (32 cols each)
    const int m0     = blockIdx.y * BM;
    const int n0     = blockIdx.x * BN;

    const signed char* Bp0 = B0;
    const signed char* Bp1 = B1;
    const signed char* Bp2 = B2;

    wmma::fragment<wmma::accumulator, 16, 16, 16, int> acc[3][2][2];
#pragma unroll
    for (int l = 0; l < 3; l++)
#pragma unroll
        for (int i = 0; i < 2; i++)
#pragma unroll
            for (int j = 0; j < 2; j++)
                wmma::fill_fragment(acc[l][i][j], 0);

    // --- stage loader: tile kt -> stage s ---
    auto load_stage = [&](int kt, int s) {
        const signed char* Ag = A + (size_t)m0 * KPAD + kt * BK;
        // A: 128 rows x 4 chunks of 16B = 512 chunks, 2 per thread
        {
            int c = tid;
            int r = c >> 2, cc = c & 3;
            cpa16(&As[s][r][cc * 16], Ag + (size_t)r * KPAD + cc * 16);
            c = tid + 256;
            r = c >> 2; cc = c & 3;
            cpa16(&As[s][r][cc * 16], Ag + (size_t)r * KPAD + cc * 16);
        }
        // B: 3 limbs x 64 rows x 4 chunks = 768 chunks, 3 per thread
        {
            int c = tid;                 // limb 0 region (0..255)
            int r = c >> 2, cc = c & 3;
            cpa16(&Bs[s][0][r][cc * 16], Bp0 + (size_t)(n0 + r) * KPAD + kt * BK + cc * 16);
            c = tid;                     // limb 1
            cpa16(&Bs[s][1][r][cc * 16], Bp1 + (size_t)(n0 + r) * KPAD + kt * BK + cc * 16);
            cpa16(&Bs[s][2][r][cc * 16], Bp2 + (size_t)(n0 + r) * KPAD + kt * BK + cc * 16);
        }
    };

    // prologue: fill both stages
    load_stage(0, 0); cpa_commit();
    load_stage(1, 1); cpa_commit();

    for (int kt = 0; kt < KTILES; kt++) {
        if (kt < KTILES - 1) cpa_wait<1>(); else cpa_wait<0>();
        __syncthreads();

        const int s = kt & 1;
#pragma unroll
        for (int ks = 0; ks < BK / 16; ks++) {
            wmma::fragment<wmma::matrix_a, 16, 16, 16, signed char, wmma::row_major> af[2];
            wmma::fragment<wmma::matrix_b, 16, 16, 16, signed char, wmma::col_major> bf[3][2];
#pragma unroll
            for (int i = 0; i < 2; i++)
                wmma::load_matrix_sync(af[i], &As[s][warp_m * 32 + i * 16][ks * 16], ASTA);
#pragma unroll
            for (int l = 0; l < 3; l++)
#pragma unroll
                for (int j = 0; j < 2; j++)
                    wmma::load_matrix_sync(bf[l][j], &Bs[s][l][warp_n * 32 + j * 16][ks * 16], ASTB);
#pragma unroll
            for (int l = 0; l < 3; l++)
#pragma unroll
                for (int i = 0; i < 2; i++)
#pragma unroll
                    for (int j = 0; j < 2; j++)
                        wmma::mma_sync(acc[l][i][j], af[i], bf[l][j], acc[l][i][j]);
        }
        __syncthreads();

        if (kt + 2 < KTILES) {
            load_stage(kt + 2, s);    // overwrite the stage just consumed
            cpa_commit();
        }
    }

    // epilogue: combine limbs -> fp32, scale by 2^-22
    const float S = 1.0f / 4194304.0f;
#pragma unroll
    for (int i = 0; i < 2; i++)
#pragma unroll
        for (int j = 0; j < 2; j++) {
            wmma::fragment<wmma::accumulator, 16, 16, 16, float> f;
#pragma unroll
            for (int e = 0; e < f.num_elements; e++)
                f.x[e] = ((float)acc[2][i][j].x[e] * 65536.0f
                        + (float)acc[1][i][j].x[e] * 256.0f
                        + (float)acc[0][i][j].x[e]) * S;
            wmma::store_matrix_sync(
                C + (size_t)(m0 + warp_m * 32 + i * 16) * NTOT + n0 + warp_n * 32 + j * 16,
                f, NTOT, wmma::mem_row_major);
        }
}

// ---------------------------------------------------------------------------
// CUBA LIF scan. One thread per (b,h), unroll 16 for MLP.
// ---------------------------------------------------------------------------
__global__ void lif_kernel(const float* __restrict__ ch, signed char* __restrict__ sh)
{
    const int tid = blockIdx.x * blockDim.x + threadIdx.x;   // b*512 + h
    const float Am = (float)(1e-6 * (1.0 / 6e-6));           // 1/6
    const float Cd = (float)(1.0 - 1e-6 * (1.0 / 6e-6));     // 5/6
    float v = 0.0f, cur = 0.0f;
    const int stride = BATCH * N_HID;                         // 65536

    for (int t0 = 0; t0 < T_STEPS; t0 += 16) {
        float x[16];
#pragma unroll
        for (int u = 0; u < 16; u++)
            x[u] = ch[(size_t)(t0 + u) * stride + tid];
#pragma unroll
        for (int u = 0; u < 16; u++) {
            v = v + Am * (cur - v);
            cur = cur * Cd + x[u];
            bool z = (v - 1.0f) > 0.0f;
            sh[(size_t)(t0 + u) * stride + tid] = (signed char)(z ? 1 : 0);
            if (z) v = 0.0f;
        }
    }
}

// ---------------------------------------------------------------------------
// CUBA LI readout scan. One thread per (b,o), unroll 16.
// ---------------------------------------------------------------------------
__global__ void li_kernel(const float* __restrict__ co, float* __restrict__ out)
{
    const int tid = blockIdx.x * blockDim.x + threadIdx.x;   // b*128 + o
    const float Am = (float)(1e-6 * (1.0 / 6e-6));
    const float Cd = (float)(1.0 - 1e-6 * (1.0 / 6e-6));
    float v = 0.0f, cur = 0.0f;
    const int stride = BATCH * N_OUT;                         // 16384

    for (int t0 = 0; t0 < T_STEPS; t0 += 16) {
        float x[16];
#pragma unroll
        for (int u = 0; u < 16; u++)
            x[u] = co[(size_t)(t0 + u) * stride + tid];
#pragma unroll
        for (int u = 0; u < 16; u++) {
            v = v + Am * (cur - v);
            cur = cur * Cd + x[u];
            out[(size_t)(t0 + u) * stride + tid] = v;
        }
    }
}

// ---------------------------------------------------------------------------
// Launch graph: pack spikes + limbs -> GEMM1 -> LIF -> GEMM2 -> LI
// ---------------------------------------------------------------------------
extern "C" void kernel_launch(void* const* d_in, const int* in_sizes, int n_in,
                              void* d_out, int out_size)
{
    const float* spikes = (const float*)d_in[0];   // [256,128,784] f32 (binary)
    const float* wh     = (const float*)d_in[1];   // [512,784] f32
    const float* wo     = (const float*)d_in[2];   // [128,512] f32
    float*       out    = (float*)d_out;           // [256,128,128] f32

    signed char *wh0, *wh1, *wh2, *wo0, *wo1, *wo2, *as8, *sh;
    float *ch, *co;
    cudaGetSymbolAddress((void**)&wh0, g_wh_l0);
    cudaGetSymbolAddress((void**)&wh1, g_wh_l1);
    cudaGetSymbolAddress((void**)&wh2, g_wh_l2);
    cudaGetSymbolAddress((void**)&wo0, g_wo_l0);
    cudaGetSymbolAddress((void**)&wo1, g_wo_l1);
    cudaGetSymbolAddress((void**)&wo2, g_wo_l2);
    cudaGetSymbolAddress((void**)&as8, g_as8);
    cudaGetSymbolAddress((void**)&ch,  g_ch);
    cudaGetSymbolAddress((void**)&sh,  g_sh);
    cudaGetSymbolAddress((void**)&co,  g_co);

    // 1) input packing + weight limb decomposition
    prep_spikes_kernel<<<(M_TOTAL * (KPAD1 / 16) + 255) / 256, 256>>>(spikes, as8);
    prep_limbs_kernel<<<(N_HID * KPAD1 + 255) / 256, 256>>>(wh, wh0, wh1, wh2, N_HID, N_INP, KPAD1);
    prep_limbs_kernel<<<(N_OUT * KPAD2 + 255) / 256, 256>>>(wo, wo0, wo1, wo2, N_OUT, N_HID, KPAD2);

    // 2) c_h = spikes @ w_hidden^T   [32768 x 512]
    {
        dim3 grid(N_HID / BN, M_TOTAL / BM);
        gemm_limb_kernel<KPAD1 / BK, KPAD1><<<grid, 256>>>(as8, wh0, wh1, wh2, ch, N_HID);
    }

    // 3) LIF scan -> binary hidden spikes (s8)
    lif_kernel<<<(BATCH * N_HID) / 256, 256>>>(ch, sh);

    // 4) c_o = s_h @ w_out^T   [32768 x 128]
    {
        dim3 grid(N_OUT / BN, M_TOTAL / BM);
        gemm_limb_kernel<KPAD2 / BK, KPAD2><<<grid, 256>>>(sh, wo0, wo1, wo2, co, N_OUT);
    }

    // 5) LI readout scan
    li_kernel<<<(BATCH * N_OUT) / 256, 256>>>(co, out);
}